// round 2
// baseline (speedup 1.0000x reference)
#include <cuda_runtime.h>
#include <cstdint>

// ContactMapGeneration: mean/s_obj + farthest point sampling + gather.
// One persistent cluster (8 CTAs x 512 threads) per batch; points held in
// registers; one cluster.sync per FPS iteration.

#define CLUSTERSZ 8
#define TPB 512
#define NPAIR 13                 // 26 point slots per thread (packed f32x2 pairs)
#define NSLOT (2 * NPAIR)
#define STRIDE (CLUSTERSZ * TPB) // 4096 threads per batch
#define MAXNP 2048
#define BIGF 1e10f

// ---------------- packed f32x2 helpers (bitwise == scalar rn) ----------------
static __device__ __forceinline__ unsigned long long pk2(float lo, float hi) {
    unsigned long long r;
    asm("mov.b64 %0, {%1,%2};" : "=l"(r) : "f"(lo), "f"(hi));
    return r;
}
static __device__ __forceinline__ void upk2(unsigned long long v, float& lo, float& hi) {
    asm("mov.b64 {%0,%1}, %2;" : "=f"(lo), "=f"(hi) : "l"(v));
}
static __device__ __forceinline__ unsigned long long add2(unsigned long long a, unsigned long long b) {
    unsigned long long r;
    asm("add.rn.f32x2 %0, %1, %2;" : "=l"(r) : "l"(a), "l"(b));
    return r;
}
static __device__ __forceinline__ unsigned long long mul2(unsigned long long a, unsigned long long b) {
    unsigned long long r;
    asm("mul.rn.f32x2 %0, %1, %2;" : "=l"(r) : "l"(a), "l"(b));
    return r;
}

// ---------------- cluster / DSMEM helpers ----------------
static __device__ __forceinline__ unsigned smem_u32(const void* p) {
    return (unsigned)__cvta_generic_to_shared(p);
}
static __device__ __forceinline__ unsigned my_ctarank() {
    unsigned r;
    asm("mov.u32 %0, %%cluster_ctarank;" : "=r"(r));
    return r;
}
static __device__ __forceinline__ void dsmem_st_u64(unsigned addr, unsigned rank, unsigned long long v) {
    asm volatile(
        "{\n\t.reg .b32 r;\n\t"
        "mapa.shared::cluster.u32 r, %0, %1;\n\t"
        "st.shared::cluster.u64 [r], %2;\n\t}"
        :: "r"(addr), "r"(rank), "l"(v) : "memory");
}
static __device__ __forceinline__ void dsmem_st_f32(unsigned addr, unsigned rank, float v) {
    asm volatile(
        "{\n\t.reg .b32 r;\n\t"
        "mapa.shared::cluster.u32 r, %0, %1;\n\t"
        "st.shared::cluster.f32 [r], %2;\n\t}"
        :: "r"(addr), "r"(rank), "f"(v) : "memory");
}
#define CLUSTER_SYNC() do { \
    asm volatile("barrier.cluster.arrive.aligned;" ::: "memory"); \
    asm volatile("barrier.cluster.wait.aligned;" ::: "memory"); \
} while (0)

// ------------------------------- kernel -------------------------------
__global__ __launch_bounds__(TPB, 1) __cluster_dims__(CLUSTERSZ, 1, 1)
void fps_contact_kernel(const float* __restrict__ mesh,
                        const float* __restrict__ cmap,
                        const int* __restrict__ initf,
                        float* __restrict__ out,
                        int B, int N, int npoint)
{
    // block-level reduction scratch
    __shared__ unsigned long long sh_wkey[16];
    __shared__ unsigned long long sh_wxy[16];
    __shared__ float              sh_wz[16];
    __shared__ float              sh_wsum[16][3];
    __shared__ float              sh_wmax[16];
    // cluster exchange slots (keys double-buffered)
    __shared__ unsigned long long sh_ckey[2][CLUSTERSZ];
    __shared__ unsigned long long sh_cxy[2][CLUSTERSZ];
    __shared__ float              sh_cz[2][CLUSTERSZ];
    __shared__ unsigned long long sh_sxy[CLUSTERSZ];
    __shared__ float              sh_sz[CLUSTERSZ];
    __shared__ float              sh_smax[CLUSTERSZ];
    // selected indices (each CTA keeps its own full copy)
    __shared__ int                sh_fps[MAXNP];

    const unsigned rank = my_ctarank();
    const int b   = blockIdx.x / CLUSTERSZ;
    const int tid = threadIdx.x;
    const int lane = tid & 31;
    const int wid  = tid >> 5;
    const int t = (int)rank * TPB + tid;           // 0..4095 within batch

    const float* mb = mesh + (size_t)b * N * 3;
    if (npoint > MAXNP) npoint = MAXNP;

    // ---------------- load points into registers (+ local float4 copy) -------
    unsigned long long PX[NPAIR], PY[NPAIR], PZ[NPAIR];
    float PD[NSLOT];
    float4 lq[NSLOT];                              // local mem: dynamic-indexed later
    float sx = 0.f, sy = 0.f, sz = 0.f;

#pragma unroll
    for (int q = 0; q < NPAIR; q++) {
        const int p0 = t + (2 * q) * STRIDE;
        const int p1 = t + (2 * q + 1) * STRIDE;
        float x0 = 0.f, y0 = 0.f, z0 = 0.f, x1 = 0.f, y1 = 0.f, z1 = 0.f;
        if (p0 < N) { x0 = mb[(size_t)p0 * 3 + 0]; y0 = mb[(size_t)p0 * 3 + 1]; z0 = mb[(size_t)p0 * 3 + 2]; }
        if (p1 < N) { x1 = mb[(size_t)p1 * 3 + 0]; y1 = mb[(size_t)p1 * 3 + 1]; z1 = mb[(size_t)p1 * 3 + 2]; }
        PX[q] = pk2(x0, x1); PY[q] = pk2(y0, y1); PZ[q] = pk2(z0, z1);
        PD[2 * q]     = (p0 < N) ? BIGF : 0.0f;
        PD[2 * q + 1] = (p1 < N) ? BIGF : 0.0f;
        lq[2 * q]     = make_float4(x0, y0, z0, 0.f);
        lq[2 * q + 1] = make_float4(x1, y1, z1, 0.f);
        sx += x0 + x1; sy += y0 + y1; sz += z0 + z1;
    }

    // ---------------- batch mean (centroid) ----------------------------------
#pragma unroll
    for (int off = 16; off; off >>= 1) {
        sx += __shfl_xor_sync(0xffffffffu, sx, off);
        sy += __shfl_xor_sync(0xffffffffu, sy, off);
        sz += __shfl_xor_sync(0xffffffffu, sz, off);
    }
    if (lane == 0) { sh_wsum[wid][0] = sx; sh_wsum[wid][1] = sy; sh_wsum[wid][2] = sz; }
    __syncthreads();
    if (wid == 0) {
        float a = (lane < 16) ? sh_wsum[lane][0] : 0.f;
        float c = (lane < 16) ? sh_wsum[lane][1] : 0.f;
        float d = (lane < 16) ? sh_wsum[lane][2] : 0.f;
#pragma unroll
        for (int off = 8; off; off >>= 1) {
            a += __shfl_xor_sync(0xffffffffu, a, off);
            c += __shfl_xor_sync(0xffffffffu, c, off);
            d += __shfl_xor_sync(0xffffffffu, d, off);
        }
        if (lane < CLUSTERSZ) {
            dsmem_st_u64(smem_u32(&sh_sxy[rank]), lane, pk2(a, c));
            dsmem_st_f32(smem_u32(&sh_sz[rank]),  lane, d);
        }
    }
    CLUSTER_SYNC();

    float tx = 0.f, ty = 0.f, tz = 0.f;
#pragma unroll
    for (int r = 0; r < CLUSTERSZ; r++) {
        float a, c; upk2(sh_sxy[r], a, c);
        tx += a; ty += c; tz += sh_sz[r];
    }
    const float cmx = tx / (float)N, cmy = ty / (float)N, cmz = tz / (float)N;

    // ---------------- s_obj = sqrt(max ||p - mean||^2) ------------------------
    {
        unsigned long long nmx = pk2(-cmx, -cmx), nmy = pk2(-cmy, -cmy), nmz = pk2(-cmz, -cmz);
        float md = 0.f;
#pragma unroll
        for (int q = 0; q < NPAIR; q++) {
            unsigned long long dx = add2(PX[q], nmx);
            unsigned long long dy = add2(PY[q], nmy);
            unsigned long long dz = add2(PZ[q], nmz);
            unsigned long long ss = add2(add2(mul2(dx, dx), mul2(dy, dy)), mul2(dz, dz));
            float d0, d1; upk2(ss, d0, d1);
            if (t + (2 * q) * STRIDE     < N) md = fmaxf(md, d0);
            if (t + (2 * q + 1) * STRIDE < N) md = fmaxf(md, d1);
        }
#pragma unroll
        for (int off = 16; off; off >>= 1)
            md = fmaxf(md, __shfl_xor_sync(0xffffffffu, md, off));
        if (lane == 0) sh_wmax[wid] = md;
        __syncthreads();
        if (wid == 0) {
            float m = (lane < 16) ? sh_wmax[lane] : 0.f;
#pragma unroll
            for (int off = 8; off; off >>= 1)
                m = fmaxf(m, __shfl_xor_sync(0xffffffffu, m, off));
            if (lane < CLUSTERSZ)
                dsmem_st_f32(smem_u32(&sh_smax[rank]), lane, m);
        }
        CLUSTER_SYNC();
    }
    float maxd = 0.f;
#pragma unroll
    for (int r = 0; r < CLUSTERSZ; r++) maxd = fmaxf(maxd, sh_smax[r]);
    const float s_obj = sqrtf(maxd);

    // ---------------- FPS main loop ------------------------------------------
    int f = initf[b];
    float cx = mb[(size_t)f * 3 + 0];
    float cy = mb[(size_t)f * 3 + 1];
    float cz = mb[(size_t)f * 3 + 2];
    int parity = 0;

    for (int i = 0; i < npoint; i++) {
        if (tid == 0) sh_fps[i] = f;

        const unsigned long long ncx = pk2(-cx, -cx);
        const unsigned long long ncy = pk2(-cy, -cy);
        const unsigned long long ncz = pk2(-cz, -cz);

        float bestd = 0.0f;
        int   bs    = 0;
#pragma unroll
        for (int q = 0; q < NPAIR; q++) {
            unsigned long long dx = add2(PX[q], ncx);   // x + (-cx) == x - cx (exact)
            unsigned long long dy = add2(PY[q], ncy);
            unsigned long long dz = add2(PZ[q], ncz);
            unsigned long long ss = add2(add2(mul2(dx, dx), mul2(dy, dy)), mul2(dz, dz));
            float d0, d1; upk2(ss, d0, d1);
            float n0 = fminf(PD[2 * q], d0);     PD[2 * q] = n0;
            if (n0 > bestd) { bestd = n0; bs = 2 * q; }
            float n1 = fminf(PD[2 * q + 1], d1); PD[2 * q + 1] = n1;
            if (n1 > bestd) { bestd = n1; bs = 2 * q + 1; }
        }

        // key: dist (>=0) in high bits, ~index in low bits -> max == argmax w/ first-idx ties
        const unsigned gi = (unsigned)(t + bs * STRIDE);
        unsigned long long key =
            ((unsigned long long)__float_as_uint(bestd) << 32) | (unsigned)(~gi);
        float4 bp = lq[bs];                       // LDL.128, latency hides under shuffles
        unsigned long long pxy = pk2(bp.x, bp.y);
        float pzv = bp.z;

        // warp butterfly (key + coord payload)
#pragma unroll
        for (int off = 16; off; off >>= 1) {
            unsigned long long ok  = __shfl_xor_sync(0xffffffffu, key, off);
            unsigned long long oxy = __shfl_xor_sync(0xffffffffu, pxy, off);
            float oz               = __shfl_xor_sync(0xffffffffu, pzv, off);
            if (ok > key) { key = ok; pxy = oxy; pzv = oz; }
        }
        if (lane == 0) { sh_wkey[wid] = key; sh_wxy[wid] = pxy; sh_wz[wid] = pzv; }
        __syncthreads();

        if (wid == 0) {
            key = (lane < 16) ? sh_wkey[lane] : 0ull;
            pxy = (lane < 16) ? sh_wxy[lane] : 0ull;
            pzv = (lane < 16) ? sh_wz[lane]  : 0.f;
#pragma unroll
            for (int off = 8; off; off >>= 1) {
                unsigned long long ok  = __shfl_xor_sync(0xffffffffu, key, off);
                unsigned long long oxy = __shfl_xor_sync(0xffffffffu, pxy, off);
                float oz               = __shfl_xor_sync(0xffffffffu, pzv, off);
                if (ok > key) { key = ok; pxy = oxy; pzv = oz; }
            }
            // lanes 0..7 fan this CTA's result out to every CTA's slot[rank]
            if (lane < CLUSTERSZ) {
                dsmem_st_u64(smem_u32(&sh_ckey[parity][rank]), lane, key);
                dsmem_st_u64(smem_u32(&sh_cxy[parity][rank]),  lane, pxy);
                dsmem_st_f32(smem_u32(&sh_cz[parity][rank]),   lane, pzv);
            }
        }
        CLUSTER_SYNC();

        // all threads reduce the 8 per-CTA candidates identically
        unsigned long long bk = sh_ckey[parity][0];
        int br = 0;
#pragma unroll
        for (int r = 1; r < CLUSTERSZ; r++) {
            unsigned long long k2 = sh_ckey[parity][r];
            if (k2 > bk) { bk = k2; br = r; }
        }
        f = (int)(~(unsigned)bk);
        float bx, by; upk2(sh_cxy[parity][br], bx, by);
        cx = bx; cy = by; cz = sh_cz[parity][br];
        parity ^= 1;
    }

    __syncthreads();

    // ---------------- gather + write output (rank-0 CTA per batch) -----------
    if (rank == 0) {
        for (int i = tid; i < npoint; i += TPB) {
            const int idx = sh_fps[i];
            const float x = mb[(size_t)idx * 3 + 0];
            const float y = mb[(size_t)idx * 3 + 1];
            const float z = mb[(size_t)idx * 3 + 2];
            const float c = cmap[(size_t)b * N + idx];
            float4 o = make_float4(c, x / s_obj, y / s_obj, z / s_obj);
            reinterpret_cast<float4*>(out)[(size_t)b * npoint + i] = o;
        }
    }
}

// ------------------------------- launch -------------------------------
extern "C" void kernel_launch(void* const* d_in, const int* in_sizes, int n_in,
                              void* d_out, int out_size) {
    const float* mesh  = (const float*)d_in[0];
    const float* cmap  = (const float*)d_in[1];
    const int*   initf = (const int*)d_in[2];

    const int B = in_sizes[2];
    const int N = in_sizes[0] / (3 * B);
    const int npoint = out_size / (4 * B);   // out = [B, npoint, 4] float32

    dim3 grid(B * CLUSTERSZ);
    dim3 block(TPB);
    fps_contact_kernel<<<grid, block>>>(mesh, cmap, initf, (float*)d_out,
                                        B, N, npoint);
}

// round 3
// speedup vs baseline: 1.2499x; 1.2499x over previous
#include <cuda_runtime.h>
#include <cstdint>

// ContactMapGeneration: mean/s_obj + farthest point sampling + gather.
// One cluster (8 CTAs x 512 threads) per batch; 25 points/thread in registers
// (24 packed-pair slots + 1 scalar tail); key-only shuffle reductions; DSMEM
// mbarrier instead of barrier.cluster on the per-iteration serial path.

#define CLUSTERSZ 8
#define TPB 512
#define NPAIR 12                 // 24 paired slots
#define TAILSLOT 24              // + 1 scalar tail slot -> 25 slots, 25*4096 >= 100000
#define STRIDE (CLUSTERSZ * TPB) // 4096 threads per batch
#define MAXNP 2048
#define BIGF 1e10f

typedef unsigned long long u64;

// ---------------- packed f32x2 helpers (bitwise == scalar rn) ----------------
static __device__ __forceinline__ u64 pk2(float lo, float hi) {
    u64 r; asm("mov.b64 %0, {%1,%2};" : "=l"(r) : "f"(lo), "f"(hi)); return r;
}
static __device__ __forceinline__ void upk2(u64 v, float& lo, float& hi) {
    asm("mov.b64 {%0,%1}, %2;" : "=f"(lo), "=f"(hi) : "l"(v));
}
static __device__ __forceinline__ u64 add2(u64 a, u64 b) {
    u64 r; asm("add.rn.f32x2 %0, %1, %2;" : "=l"(r) : "l"(a), "l"(b)); return r;
}
static __device__ __forceinline__ u64 mul2(u64 a, u64 b) {
    u64 r; asm("mul.rn.f32x2 %0, %1, %2;" : "=l"(r) : "l"(a), "l"(b)); return r;
}

// ---------------- cluster / DSMEM helpers ----------------
static __device__ __forceinline__ unsigned smem_u32(const void* p) {
    return (unsigned)__cvta_generic_to_shared(p);
}
static __device__ __forceinline__ unsigned my_ctarank() {
    unsigned r; asm("mov.u32 %0, %%cluster_ctarank;" : "=r"(r)); return r;
}
static __device__ __forceinline__ void dsmem_st_u64(unsigned addr, unsigned rank, u64 v) {
    asm volatile(
        "{\n\t.reg .b32 r;\n\t"
        "mapa.shared::cluster.u32 r, %0, %1;\n\t"
        "st.shared::cluster.u64 [r], %2;\n\t}"
        :: "r"(addr), "r"(rank), "l"(v) : "memory");
}
static __device__ __forceinline__ void dsmem_st_f32(unsigned addr, unsigned rank, float v) {
    asm volatile(
        "{\n\t.reg .b32 r;\n\t"
        "mapa.shared::cluster.u32 r, %0, %1;\n\t"
        "st.shared::cluster.f32 [r], %2;\n\t}"
        :: "r"(addr), "r"(rank), "f"(v) : "memory");
}
static __device__ __forceinline__ void mbar_arrive_remote(unsigned addr, unsigned rank) {
    asm volatile(
        "{\n\t.reg .b32 r;\n\t"
        "mapa.shared::cluster.u32 r, %0, %1;\n\t"
        "mbarrier.arrive.release.cluster.shared::cluster.b64 _, [r];\n\t}"
        :: "r"(addr), "r"(rank) : "memory");
}
static __device__ __forceinline__ void mbar_wait(unsigned addr, unsigned parity) {
    asm volatile(
        "{\n\t.reg .pred P;\n"
        "LW%=:\n\t"
        "mbarrier.try_wait.parity.acquire.cluster.shared::cta.b64 P, [%0], %1;\n\t"
        "@!P bra LW%=;\n\t}"
        :: "r"(addr), "r"(parity) : "memory");
}
#define CLUSTER_SYNC() do { \
    asm volatile("barrier.cluster.arrive.aligned;" ::: "memory"); \
    asm volatile("barrier.cluster.wait.aligned;" ::: "memory"); \
} while (0)

// ------------------------------- kernel -------------------------------
__global__ __launch_bounds__(TPB, 1) __cluster_dims__(CLUSTERSZ, 1, 1)
void fps_contact_kernel(const float* __restrict__ mesh,
                        const float* __restrict__ cmap,
                        const int* __restrict__ initf,
                        float* __restrict__ out,
                        int B, int N, int npoint)
{
    // per-warp reduce scratch
    __shared__ u64    sh_wkey[16];
    __shared__ float4 sh_wxyz[16];
    // cluster exchange slots, double-buffered, remotely written
    __shared__ u64    sh_ckey[2][CLUSTERSZ];
    __shared__ u64    sh_cxy[2][CLUSTERSZ];
    __shared__ float  sh_cz[2][CLUSTERSZ];
    // stats scratch
    __shared__ float  sh_wsum[16][3];
    __shared__ float  sh_wmax[16];
    __shared__ u64    sh_sxy[CLUSTERSZ];
    __shared__ float  sh_sz[CLUSTERSZ];
    __shared__ float  sh_smax[CLUSTERSZ];
    // selected indices (rank-0 CTA keeps them)
    __shared__ int    sh_fps[MAXNP];
    __shared__ u64    mbar;

    const unsigned rank = my_ctarank();
    const int b    = blockIdx.x / CLUSTERSZ;
    const int tid  = threadIdx.x;
    const int lane = tid & 31;
    const int wid  = tid >> 5;
    const int t    = (int)rank * TPB + tid;        // 0..4095 within batch
    const unsigned mb_addr = smem_u32(&mbar);

    const float* mb = mesh + (size_t)b * N * 3;
    if (npoint > MAXNP) npoint = MAXNP;

    if (tid == 0) {
        asm volatile("mbarrier.init.shared::cta.b64 [%0], %1;"
                     :: "r"(mb_addr), "r"(CLUSTERSZ) : "memory");
    }

    // ---------------- load points into registers (+ local coord table) -------
    u64   PX[NPAIR], PY[NPAIR], PZ[NPAIR];
    float PDa[NPAIR], PDb[NPAIR];                  // even/odd slot min-dists
    float4 lq[TAILSLOT + 1];                       // local mem, dynamic-indexed by winner lane
    float tx3, ty3, tz3, PDt;                      // tail slot
    float sx = 0.f, sy = 0.f, sz = 0.f;

#pragma unroll
    for (int q = 0; q < NPAIR; q++) {
        const int p0 = t + (2 * q) * STRIDE;       // always < N (max 98303)
        const int p1 = t + (2 * q + 1) * STRIDE;
        float x0 = mb[(size_t)p0 * 3 + 0], y0 = mb[(size_t)p0 * 3 + 1], z0 = mb[(size_t)p0 * 3 + 2];
        float x1 = mb[(size_t)p1 * 3 + 0], y1 = mb[(size_t)p1 * 3 + 1], z1 = mb[(size_t)p1 * 3 + 2];
        PX[q] = pk2(x0, x1); PY[q] = pk2(y0, y1); PZ[q] = pk2(z0, z1);
        PDa[q] = BIGF; PDb[q] = BIGF;
        lq[2 * q]     = make_float4(x0, y0, z0, 0.f);
        lq[2 * q + 1] = make_float4(x1, y1, z1, 0.f);
        sx += x0 + x1; sy += y0 + y1; sz += z0 + z1;
    }
    {
        const int pt = t + TAILSLOT * STRIDE;
        const bool v = pt < N;
        tx3 = v ? mb[(size_t)pt * 3 + 0] : 0.f;
        ty3 = v ? mb[(size_t)pt * 3 + 1] : 0.f;
        tz3 = v ? mb[(size_t)pt * 3 + 2] : 0.f;
        PDt = v ? BIGF : 0.0f;
        lq[TAILSLOT] = make_float4(tx3, ty3, tz3, 0.f);
        sx += tx3; sy += ty3; sz += tz3;
    }

    // ---------------- batch mean (centroid) ----------------------------------
#pragma unroll
    for (int off = 16; off; off >>= 1) {
        sx += __shfl_xor_sync(0xffffffffu, sx, off);
        sy += __shfl_xor_sync(0xffffffffu, sy, off);
        sz += __shfl_xor_sync(0xffffffffu, sz, off);
    }
    if (lane == 0) { sh_wsum[wid][0] = sx; sh_wsum[wid][1] = sy; sh_wsum[wid][2] = sz; }
    __syncthreads();
    if (wid == 0) {
        float a = (lane < 16) ? sh_wsum[lane][0] : 0.f;
        float c = (lane < 16) ? sh_wsum[lane][1] : 0.f;
        float d = (lane < 16) ? sh_wsum[lane][2] : 0.f;
#pragma unroll
        for (int off = 8; off; off >>= 1) {
            a += __shfl_xor_sync(0xffffffffu, a, off);
            c += __shfl_xor_sync(0xffffffffu, c, off);
            d += __shfl_xor_sync(0xffffffffu, d, off);
        }
        if (lane < CLUSTERSZ) {
            dsmem_st_u64(smem_u32(&sh_sxy[rank]), lane, pk2(a, c));
            dsmem_st_f32(smem_u32(&sh_sz[rank]),  lane, d);
        }
    }
    CLUSTER_SYNC();   // also publishes mbarrier.init cluster-wide

    float txs = 0.f, tys = 0.f, tzs = 0.f;
#pragma unroll
    for (int r = 0; r < CLUSTERSZ; r++) {
        float a, c; upk2(sh_sxy[r], a, c);
        txs += a; tys += c; tzs += sh_sz[r];
    }
    const float cmx = txs / (float)N, cmy = tys / (float)N, cmz = tzs / (float)N;

    // ---------------- s_obj = sqrt(max ||p - mean||^2) ------------------------
    {
        u64 nmx = pk2(-cmx, -cmx), nmy = pk2(-cmy, -cmy), nmz = pk2(-cmz, -cmz);
        float md = 0.f;
#pragma unroll
        for (int q = 0; q < NPAIR; q++) {
            u64 dx = add2(PX[q], nmx);
            u64 dy = add2(PY[q], nmy);
            u64 dz = add2(PZ[q], nmz);
            u64 ss = add2(add2(mul2(dx, dx), mul2(dy, dy)), mul2(dz, dz));
            float d0, d1; upk2(ss, d0, d1);
            md = fmaxf(md, fmaxf(d0, d1));
        }
        if (t + TAILSLOT * STRIDE < N) {
            float dxs = __fadd_rn(tx3, -cmx);
            float dys = __fadd_rn(ty3, -cmy);
            float dzs = __fadd_rn(tz3, -cmz);
            float ds = __fadd_rn(__fadd_rn(__fmul_rn(dxs, dxs), __fmul_rn(dys, dys)),
                                 __fmul_rn(dzs, dzs));
            md = fmaxf(md, ds);
        }
#pragma unroll
        for (int off = 16; off; off >>= 1)
            md = fmaxf(md, __shfl_xor_sync(0xffffffffu, md, off));
        if (lane == 0) sh_wmax[wid] = md;
        __syncthreads();
        if (wid == 0) {
            float m = (lane < 16) ? sh_wmax[lane] : 0.f;
#pragma unroll
            for (int off = 8; off; off >>= 1)
                m = fmaxf(m, __shfl_xor_sync(0xffffffffu, m, off));
            if (lane < CLUSTERSZ)
                dsmem_st_f32(smem_u32(&sh_smax[rank]), lane, m);
        }
        CLUSTER_SYNC();
    }
    float maxd = 0.f;
#pragma unroll
    for (int r = 0; r < CLUSTERSZ; r++) maxd = fmaxf(maxd, sh_smax[r]);
    const float s_obj = sqrtf(maxd);

    // ---------------- FPS main loop ------------------------------------------
    int f = initf[b];
    u64 ncx, ncy, ncz;                             // packed (-c, -c)
    {
        float icx = mb[(size_t)f * 3 + 0];
        float icy = mb[(size_t)f * 3 + 1];
        float icz = mb[(size_t)f * 3 + 2];
        ncx = pk2(-icx, -icx); ncy = pk2(-icy, -icy); ncz = pk2(-icz, -icz);
    }
    unsigned ph = 0;
    int par = 0;

    for (int i = 0; i < npoint; i++) {
        if (rank == 0 && tid == 0) sh_fps[i] = f;
        if (i + 1 == npoint) break;                // last centroid recorded; no scan needed

        float best0 = -1.0f, best1 = -1.0f;
        int   bs0 = 0, bs1 = 1;
#pragma unroll
        for (int q = 0; q < NPAIR; q++) {
            u64 dx = add2(PX[q], ncx);             // x + (-cx) == x - cx (exact)
            u64 dy = add2(PY[q], ncy);
            u64 dz = add2(PZ[q], ncz);
            u64 ss = add2(add2(mul2(dx, dx), mul2(dy, dy)), mul2(dz, dz));
            float d0, d1; upk2(ss, d0, d1);
            float n0 = fminf(PDa[q], d0); PDa[q] = n0;
            if (n0 > best0) { best0 = n0; bs0 = 2 * q; }
            float n1 = fminf(PDb[q], d1); PDb[q] = n1;
            if (n1 > best1) { best1 = n1; bs1 = 2 * q + 1; }
        }
        {   // tail slot (chain0; strict > keeps earlier index on ties)
            float nx, ny, nz, dum;
            upk2(ncx, nx, dum); upk2(ncy, ny, dum); upk2(ncz, nz, dum);
            float dxs = __fadd_rn(tx3, nx);
            float dys = __fadd_rn(ty3, ny);
            float dzs = __fadd_rn(tz3, nz);
            float ds = __fadd_rn(__fadd_rn(__fmul_rn(dxs, dxs), __fmul_rn(dys, dys)),
                                 __fmul_rn(dzs, dzs));
            float nt = fminf(PDt, ds); PDt = nt;
            if (nt > best0) { best0 = nt; bs0 = TAILSLOT; }
        }
        // merge chains with exact first-index tie-break
        float best; int bs;
        if (best1 > best0 || (best1 == best0 && bs1 < bs0)) { best = best1; bs = bs1; }
        else                                                { best = best0; bs = bs0; }

        const unsigned gidx = (unsigned)t + (unsigned)bs * STRIDE;
        u64 key = ((u64)__float_as_uint(best) << 32) | (unsigned)(~gidx);

        // warp butterfly: key only (dist>=0 -> uint order == float order; ~idx -> first index on ties)
#pragma unroll
        for (int off = 16; off; off >>= 1) {
            u64 ok = __shfl_xor_sync(0xffffffffu, key, off);
            if (ok > key) key = ok;
        }
        // winner lane alone materializes coords from local table
        const unsigned wg = ~(unsigned)key;        // winning global idx in this warp
        if (lane == (int)(wg & 31u)) {
            float4 p = lq[wg >> 12];               // slot = gidx / 4096
            sh_wkey[wid] = key;
            sh_wxyz[wid] = p;
        }
        __syncthreads();

        // threads 0..7: reduce 16 warp winners, push CTA result to CTA[tid]
        if (tid < CLUSTERSZ) {
            u64 bk = sh_wkey[0]; int j = 0;
#pragma unroll
            for (int w = 1; w < 16; w++) {
                u64 k2 = sh_wkey[w];
                if (k2 > bk) { bk = k2; j = w; }
            }
            float4 p = sh_wxyz[j];
            dsmem_st_u64(smem_u32(&sh_ckey[par][rank]), (unsigned)tid, bk);
            dsmem_st_u64(smem_u32(&sh_cxy[par][rank]),  (unsigned)tid, pk2(p.x, p.y));
            dsmem_st_f32(smem_u32(&sh_cz[par][rank]),   (unsigned)tid, p.z);
            mbar_arrive_remote(mb_addr, (unsigned)tid);
        }

        mbar_wait(mb_addr, ph);
        ph ^= 1;

        // all threads reduce the 8 per-CTA candidates identically
        u64 bk = sh_ckey[par][0]; int br = 0;
#pragma unroll
        for (int r = 1; r < CLUSTERSZ; r++) {
            u64 k2 = sh_ckey[par][r];
            if (k2 > bk) { bk = k2; br = r; }
        }
        f = (int)(~(unsigned)bk);
        float bx, by; upk2(sh_cxy[par][br], bx, by);
        float bz = sh_cz[par][br];
        ncx = pk2(-bx, -bx); ncy = pk2(-by, -by); ncz = pk2(-bz, -bz);
        par ^= 1;
    }

    __syncthreads();

    // ---------------- gather + write output (rank-0 CTA per batch) -----------
    if (rank == 0) {
        for (int i = tid; i < npoint; i += TPB) {
            const int idx = sh_fps[i];
            const float x = mb[(size_t)idx * 3 + 0];
            const float y = mb[(size_t)idx * 3 + 1];
            const float z = mb[(size_t)idx * 3 + 2];
            const float c = cmap[(size_t)b * N + idx];
            float4 o = make_float4(c, x / s_obj, y / s_obj, z / s_obj);
            reinterpret_cast<float4*>(out)[(size_t)b * npoint + i] = o;
        }
    }
}

// ------------------------------- launch -------------------------------
extern "C" void kernel_launch(void* const* d_in, const int* in_sizes, int n_in,
                              void* d_out, int out_size) {
    const float* mesh  = (const float*)d_in[0];
    const float* cmap  = (const float*)d_in[1];
    const int*   initf = (const int*)d_in[2];

    const int B = in_sizes[2];
    const int N = in_sizes[0] / (3 * B);
    const int npoint = out_size / (4 * B);   // out = [B, npoint, 4] float32

    dim3 grid(B * CLUSTERSZ);
    dim3 block(TPB);
    fps_contact_kernel<<<grid, block>>>(mesh, cmap, initf, (float*)d_out,
                                        B, N, npoint);
}